// round 3
// baseline (speedup 1.0000x reference)
#include <cuda_runtime.h>
#include <math.h>

#define BB 128
#define HH 4
#define NN 4096
#define WW 128
#define CTRL 1560          // H*(3*W+6)
#define EPSF 1e-8f

// ---------------- scratch (static device globals; no allocs allowed) -------
static __device__ float g_keys [BB*HH*WW];
static __device__ float g_erase[BB*HH*WW];
static __device__ float g_write[BB*HH*WW];
static __device__ float g_keynorm[BB*HH];
static __device__ float g_beta [BB*HH];
static __device__ float g_gate [BB*HH];
static __device__ float g_gamma[BB*HH];
static __device__ float g_shift[BB*HH*3];
static __device__ float g_prev [HH*NN];
static __device__ float g_scores[BB*HH*NN];
static __device__ float g_wd    [BB*HH*NN];

__device__ __forceinline__ float softplusf(float x) {
    return (x > 20.f) ? x : log1pf(expf(x));
}
__device__ __forceinline__ float sigmoidf(float x) {
    return 1.f / (1.f + expf(-x));
}

// -------------------- Kernel A: control activations ------------------------
// grid: B*H blocks of 128 threads (one per w)
__global__ void kA_controls(const float* __restrict__ controls) {
    int bh = blockIdx.x;
    int b = bh >> 2, h = bh & 3;
    int w = threadIdx.x;
    const float* c = controls + b * CTRL;

    float k = tanhf(c[h * WW + w]);
    g_keys [bh * WW + w] = k;
    g_erase[bh * WW + w] = sigmoidf(c[512 + h * WW + w]);
    g_write[bh * WW + w] = tanhf(c[1024 + h * WW + w]);

    // block-reduce k*k (128 threads = 4 warps)
    float s = k * k;
    #pragma unroll
    for (int o = 16; o; o >>= 1) s += __shfl_xor_sync(0xFFFFFFFFu, s, o);
    __shared__ float red[4];
    int lane = w & 31, wid = w >> 5;
    if (lane == 0) red[wid] = s;
    __syncthreads();
    if (w == 0) {
        float kn = sqrtf(red[0] + red[1] + red[2] + red[3]);
        g_keynorm[bh] = kn;
        g_beta[bh]  = softplusf(c[1536 + h]);
        g_gate[bh]  = sigmoidf(c[1540 + h]);
        g_gamma[bh] = 1.f + softplusf(c[1556 + h]);
        float a0 = c[1544 + h * 3 + 0];
        float a1 = c[1544 + h * 3 + 1];
        float a2 = c[1544 + h * 3 + 2];
        float m = fmaxf(a0, fmaxf(a1, a2));
        float e0 = expf(a0 - m), e1 = expf(a1 - m), e2 = expf(a2 - m);
        float inv = 1.f / (e0 + e1 + e2);
        g_shift[bh * 3 + 0] = e0 * inv;
        g_shift[bh * 3 + 1] = e1 * inv;
        g_shift[bh * 3 + 2] = e2 * inv;
    }
}

// ---------------- block reduce helpers (generic warp count) ----------------
template<int NWARPS>
__device__ __forceinline__ float blockReduceSum(float v, float* red, int tid) {
    int lane = tid & 31, wid = tid >> 5;
    #pragma unroll
    for (int o = 16; o; o >>= 1) v += __shfl_xor_sync(0xFFFFFFFFu, v, o);
    if (lane == 0) red[wid] = v;
    __syncthreads();
    float r = (tid < NWARPS) ? red[tid] : 0.f;
    if (wid == 0) {
        #pragma unroll
        for (int o = 16; o; o >>= 1) r += __shfl_xor_sync(0xFFFFFFFFu, r, o);
        if (lane == 0) red[0] = r;
    }
    __syncthreads();
    float out = red[0];
    __syncthreads();
    return out;
}
template<int NWARPS>
__device__ __forceinline__ float blockReduceMax(float v, float* red, int tid) {
    int lane = tid & 31, wid = tid >> 5;
    #pragma unroll
    for (int o = 16; o; o >>= 1) v = fmaxf(v, __shfl_xor_sync(0xFFFFFFFFu, v, o));
    if (lane == 0) red[wid] = v;
    __syncthreads();
    float r = (tid < NWARPS) ? red[tid] : -INFINITY;
    if (wid == 0) {
        #pragma unroll
        for (int o = 16; o; o >>= 1) r = fmaxf(r, __shfl_xor_sync(0xFFFFFFFFu, r, o));
        if (lane == 0) red[0] = r;
    }
    __syncthreads();
    float out = red[0];
    __syncthreads();
    return out;
}

// -------------- Kernel P: prev_weights = softmax(bias) over N --------------
// grid: H blocks of 1024 threads, 4 elems/thread
__global__ void kP_prev(const float* __restrict__ bias) {
    __shared__ float red[32];
    int h = blockIdx.x, tid = threadIdx.x;
    float v[4], mx = -INFINITY;
    #pragma unroll
    for (int k = 0; k < 4; k++) {
        v[k] = bias[h * NN + tid + k * 1024];
        mx = fmaxf(mx, v[k]);
    }
    mx = blockReduceMax<32>(mx, red, tid);
    float s = 0.f;
    #pragma unroll
    for (int k = 0; k < 4; k++) { v[k] = expf(v[k] - mx); s += v[k]; }
    s = blockReduceSum<32>(s, red, tid);
    float inv = 1.f / s;
    #pragma unroll
    for (int k = 0; k < 4; k++)
        g_prev[h * NN + tid + k * 1024] = v[k] * inv;
}

// -------------- Kernel B: memory pass 1 -> cosine scores -------------------
// grid: (64, B), block 256 (8 warps). Each warp: 8 contiguous rows.
// Each lane owns W-slice [lane*4, lane*4+4); keys held in registers.
__global__ void kB_scores(const float* __restrict__ memory) {
    int b = blockIdx.y;
    int tid = threadIdx.x;
    int lane = tid & 31, warp = tid >> 5;

    float4 kk[HH];
    float kn[HH];
    #pragma unroll
    for (int h = 0; h < HH; h++) {
        kk[h] = *(const float4*)&g_keys[(b * HH + h) * WW + lane * 4];
        kn[h] = g_keynorm[b * HH + h];
    }

    int wi = blockIdx.x * 8 + warp;     // 0..511
    int n0 = wi * 8;
    #pragma unroll
    for (int r = 0; r < 8; r++) {
        int n = n0 + r;
        const float4 m = *(const float4*)(memory + ((size_t)(b * NN + n)) * WW + lane * 4);
        float m2 = m.x*m.x + m.y*m.y + m.z*m.z + m.w*m.w;
        float d0 = m.x*kk[0].x + m.y*kk[0].y + m.z*kk[0].z + m.w*kk[0].w;
        float d1 = m.x*kk[1].x + m.y*kk[1].y + m.z*kk[1].z + m.w*kk[1].w;
        float d2 = m.x*kk[2].x + m.y*kk[2].y + m.z*kk[2].z + m.w*kk[2].w;
        float d3 = m.x*kk[3].x + m.y*kk[3].y + m.z*kk[3].z + m.w*kk[3].w;
        #pragma unroll
        for (int o = 16; o; o >>= 1) {
            m2 += __shfl_xor_sync(0xFFFFFFFFu, m2, o);
            d0 += __shfl_xor_sync(0xFFFFFFFFu, d0, o);
            d1 += __shfl_xor_sync(0xFFFFFFFFu, d1, o);
            d2 += __shfl_xor_sync(0xFFFFFFFFu, d2, o);
            d3 += __shfl_xor_sync(0xFFFFFFFFu, d3, o);
        }
        if (lane == 0) {
            float nm = sqrtf(m2);
            g_scores[(b * HH + 0) * NN + n] = d0 / (kn[0] * nm + EPSF);
            g_scores[(b * HH + 1) * NN + n] = d1 / (kn[1] * nm + EPSF);
            g_scores[(b * HH + 2) * NN + n] = d2 / (kn[2] * nm + EPSF);
            g_scores[(b * HH + 3) * NN + n] = d3 / (kn[3] * nm + EPSF);
        }
    }
}

// -------------- Kernel C: softmax/interp/shift/sharpen/renorm --------------
// grid: B*H blocks of 512 threads, 8 elems/thread (strided), smem row of N.
__global__ void kC_weights() {
    __shared__ float sm[NN];
    __shared__ float red[16];
    int bh = blockIdx.x;
    int h = bh & 3;
    int tid = threadIdx.x;

    float beta  = g_beta[bh];
    float gate  = g_gate[bh];
    float gamma = g_gamma[bh];
    float s0 = g_shift[bh * 3 + 0];
    float s1 = g_shift[bh * 3 + 1];
    float s2 = g_shift[bh * 3 + 2];

    float v[8], mx = -INFINITY;
    #pragma unroll
    for (int k = 0; k < 8; k++) {
        v[k] = g_scores[bh * NN + tid + k * 512] * beta;
        mx = fmaxf(mx, v[k]);
    }
    mx = blockReduceMax<16>(mx, red, tid);
    float s = 0.f;
    #pragma unroll
    for (int k = 0; k < 8; k++) { v[k] = expf(v[k] - mx); s += v[k]; }
    s = blockReduceSum<16>(s, red, tid);
    float invS = 1.f / s;
    float omg = 1.f - gate;
    #pragma unroll
    for (int k = 0; k < 8; k++) {
        int n = tid + k * 512;
        sm[n] = gate * v[k] * invS + omg * g_prev[h * NN + n];
    }
    __syncthreads();
    float t = 0.f, ws[8];
    #pragma unroll
    for (int k = 0; k < 8; k++) {
        int n = tid + k * 512;
        float wsh = s0 * sm[(n - 1) & (NN - 1)] + s1 * sm[n] + s2 * sm[(n + 1) & (NN - 1)];
        // wsh >= 0 always (convex-ish combo of nonneg weights)
        float p = exp2f(gamma * log2f(wsh));   // wsh==0 -> -inf -> 0, matches fp32 ref underflow
        ws[k] = p;
        t += p;
    }
    t = blockReduceSum<16>(t, red, tid);
    float invT = 1.f / (t + EPSF);
    #pragma unroll
    for (int k = 0; k < 8; k++)
        g_wd[bh * NN + tid + k * 512] = ws[k] * invT;
}

// -------------- Kernel D: memory pass 2 -> erase/update/write --------------
// grid: (32, B), block 256 (8 warps). Each warp: 16 contiguous rows.
// Each lane owns W-slice [lane*4, lane*4+4); erase/write acts in registers.
__global__ void kD_apply(const float* __restrict__ memory, float* __restrict__ out) {
    int b = blockIdx.y;
    int tid = threadIdx.x;
    int lane = tid & 31, warp = tid >> 5;

    float4 ea[HH], wa[HH];
    #pragma unroll
    for (int h = 0; h < HH; h++) {
        ea[h] = *(const float4*)&g_erase[(b * HH + h) * WW + lane * 4];
        wa[h] = *(const float4*)&g_write[(b * HH + h) * WW + lane * 4];
    }

    int wi = blockIdx.x * 8 + warp;    // 0..255
    int n0 = wi * 16;
    #pragma unroll 4
    for (int r = 0; r < 16; r++) {
        int n = n0 + r;
        float wd0 = __ldg(&g_wd[(b * HH + 0) * NN + n]);
        float wd1 = __ldg(&g_wd[(b * HH + 1) * NN + n]);
        float wd2 = __ldg(&g_wd[(b * HH + 2) * NN + n]);
        float wd3 = __ldg(&g_wd[(b * HH + 3) * NN + n]);
        size_t off = ((size_t)(b * NN + n)) * WW + lane * 4;
        const float4 m = *(const float4*)(memory + off);
        float4 o;
        o.x = m.x * ((1.f - wd0*ea[0].x) * (1.f - wd1*ea[1].x) * (1.f - wd2*ea[2].x) * (1.f - wd3*ea[3].x))
            + (wd0*wa[0].x + wd1*wa[1].x + wd2*wa[2].x + wd3*wa[3].x);
        o.y = m.y * ((1.f - wd0*ea[0].y) * (1.f - wd1*ea[1].y) * (1.f - wd2*ea[2].y) * (1.f - wd3*ea[3].y))
            + (wd0*wa[0].y + wd1*wa[1].y + wd2*wa[2].y + wd3*wa[3].y);
        o.z = m.z * ((1.f - wd0*ea[0].z) * (1.f - wd1*ea[1].z) * (1.f - wd2*ea[2].z) * (1.f - wd3*ea[3].z))
            + (wd0*wa[0].z + wd1*wa[1].z + wd2*wa[2].z + wd3*wa[3].z);
        o.w = m.w * ((1.f - wd0*ea[0].w) * (1.f - wd1*ea[1].w) * (1.f - wd2*ea[2].w) * (1.f - wd3*ea[3].w))
            + (wd0*wa[0].w + wd1*wa[1].w + wd2*wa[2].w + wd3*wa[3].w);
        *(float4*)(out + off) = o;
    }
}

// ---------------------------------------------------------------------------
extern "C" void kernel_launch(void* const* d_in, const int* in_sizes, int n_in,
                              void* d_out, int out_size) {
    const float* memory   = (const float*)d_in[0];   // [B,N,W]
    const float* controls = (const float*)d_in[1];   // [B, H*(3W+6)]
    const float* bias     = (const float*)d_in[2];   // [1,H,N]
    float* out = (float*)d_out;                      // [B,N,W]

    kA_controls<<<BB * HH, 128>>>(controls);
    kP_prev<<<HH, 1024>>>(bias);
    kB_scores<<<dim3(64, BB), 256>>>(memory);
    kC_weights<<<BB * HH, 512>>>();
    kD_apply<<<dim3(32, BB), 256>>>(memory, out);
}

// round 5
// speedup vs baseline: 1.0965x; 1.0965x over previous
#include <cuda_runtime.h>
#include <math.h>

#define BB 128
#define HH 4
#define NN 4096
#define WW 128
#define CTRL 1560          // H*(3*W+6)
#define EPSF 1e-8f

// ---------------- scratch (static device globals; no allocs allowed) -------
static __device__ float g_keys [BB*HH*WW];
static __device__ float g_erase[BB*HH*WW];
static __device__ float g_write[BB*HH*WW];
static __device__ float g_keynorm[BB*HH];
static __device__ float g_beta [BB*HH];
static __device__ float g_gate [BB*HH];
static __device__ float g_gamma[BB*HH];
static __device__ float g_shift[BB*HH*3];
static __device__ float g_prev [HH*NN];
static __device__ float g_scores[BB*HH*NN];
static __device__ float g_wd    [BB*HH*NN];

__device__ __forceinline__ float softplusf(float x) {
    return (x > 20.f) ? x : log1pf(expf(x));
}
__device__ __forceinline__ float sigmoidf(float x) {
    return 1.f / (1.f + expf(-x));
}

// -------------------- Kernel A: control activations ------------------------
__global__ void kA_controls(const float* __restrict__ controls) {
    int bh = blockIdx.x;
    int b = bh >> 2, h = bh & 3;
    int w = threadIdx.x;
    const float* c = controls + b * CTRL;

    float k = tanhf(c[h * WW + w]);
    g_keys [bh * WW + w] = k;
    g_erase[bh * WW + w] = sigmoidf(c[512 + h * WW + w]);
    g_write[bh * WW + w] = tanhf(c[1024 + h * WW + w]);

    float s = k * k;
    #pragma unroll
    for (int o = 16; o; o >>= 1) s += __shfl_xor_sync(0xFFFFFFFFu, s, o);
    __shared__ float red[4];
    int lane = w & 31, wid = w >> 5;
    if (lane == 0) red[wid] = s;
    __syncthreads();
    if (w == 0) {
        float kn = sqrtf(red[0] + red[1] + red[2] + red[3]);
        g_keynorm[bh] = kn;
        g_beta[bh]  = softplusf(c[1536 + h]);
        g_gate[bh]  = sigmoidf(c[1540 + h]);
        g_gamma[bh] = 1.f + softplusf(c[1556 + h]);
        float a0 = c[1544 + h * 3 + 0];
        float a1 = c[1544 + h * 3 + 1];
        float a2 = c[1544 + h * 3 + 2];
        float m = fmaxf(a0, fmaxf(a1, a2));
        float e0 = expf(a0 - m), e1 = expf(a1 - m), e2 = expf(a2 - m);
        float inv = 1.f / (e0 + e1 + e2);
        g_shift[bh * 3 + 0] = e0 * inv;
        g_shift[bh * 3 + 1] = e1 * inv;
        g_shift[bh * 3 + 2] = e2 * inv;
    }
}

// ---------------- block reduce helpers ----------------
template<int NWARPS>
__device__ __forceinline__ float blockReduceSum(float v, float* red, int tid) {
    int lane = tid & 31, wid = tid >> 5;
    #pragma unroll
    for (int o = 16; o; o >>= 1) v += __shfl_xor_sync(0xFFFFFFFFu, v, o);
    if (lane == 0) red[wid] = v;
    __syncthreads();
    float r = (tid < NWARPS) ? red[tid] : 0.f;
    if (wid == 0) {
        #pragma unroll
        for (int o = 16; o; o >>= 1) r += __shfl_xor_sync(0xFFFFFFFFu, r, o);
        if (lane == 0) red[0] = r;
    }
    __syncthreads();
    float out = red[0];
    __syncthreads();
    return out;
}
template<int NWARPS>
__device__ __forceinline__ float blockReduceMax(float v, float* red, int tid) {
    int lane = tid & 31, wid = tid >> 5;
    #pragma unroll
    for (int o = 16; o; o >>= 1) v = fmaxf(v, __shfl_xor_sync(0xFFFFFFFFu, v, o));
    if (lane == 0) red[wid] = v;
    __syncthreads();
    float r = (tid < NWARPS) ? red[tid] : -INFINITY;
    if (wid == 0) {
        #pragma unroll
        for (int o = 16; o; o >>= 1) r = fmaxf(r, __shfl_xor_sync(0xFFFFFFFFu, r, o));
        if (lane == 0) red[0] = r;
    }
    __syncthreads();
    float out = red[0];
    __syncthreads();
    return out;
}

// -------------- Kernel P: prev_weights = softmax(bias) over N --------------
__global__ void kP_prev(const float* __restrict__ bias) {
    __shared__ float red[32];
    int h = blockIdx.x, tid = threadIdx.x;
    float v[4], mx = -INFINITY;
    #pragma unroll
    for (int k = 0; k < 4; k++) {
        v[k] = bias[h * NN + tid + k * 1024];
        mx = fmaxf(mx, v[k]);
    }
    mx = blockReduceMax<32>(mx, red, tid);
    float s = 0.f;
    #pragma unroll
    for (int k = 0; k < 4; k++) { v[k] = expf(v[k] - mx); s += v[k]; }
    s = blockReduceSum<32>(s, red, tid);
    float inv = 1.f / s;
    #pragma unroll
    for (int k = 0; k < 4; k++)
        g_prev[h * NN + tid + k * 1024] = v[k] * inv;
}

// -------------- Kernel B: memory pass 1 -> cosine scores -------------------
// 8 lanes per row, 4 rows per warp-group. Reduction: 3 butterfly levels only.
// grid (32, B), block 256 (8 warps). Each warp: 16 rows in 4 groups of 4.
__global__ void kB_scores(const float* __restrict__ memory) {
    int b = blockIdx.y;
    int tid = threadIdx.x;
    int lane = tid & 31, warp = tid >> 5;
    int sub  = lane & 7;     // which 16-float chunk of the row this lane owns
    int rsel = lane >> 3;    // which of the 4 rows in a group

    // keys for this lane's W-chunk: 4 heads x 16 floats = 16 float4 in regs
    float4 kk[HH][4];
    float  kn[HH];
    #pragma unroll
    for (int h = 0; h < HH; h++) {
        const float* kp = &g_keys[(b * HH + h) * WW + sub * 16];
        #pragma unroll
        for (int i = 0; i < 4; i++) kk[h][i] = *(const float4*)(kp + 4 * i);
        kn[h] = g_keynorm[b * HH + h];
    }

    int wi = blockIdx.x * 8 + warp;   // 0..255
    int n0 = wi * 16;
    #pragma unroll
    for (int g = 0; g < 4; g++) {
        int n = n0 + g * 4 + rsel;
        const float* rp = memory + ((size_t)(b * NN + n)) * WW + sub * 16;
        float4 m[4];
        #pragma unroll
        for (int i = 0; i < 4; i++) m[i] = __ldcs((const float4*)(rp + 4 * i));

        float m2 = 0.f, d0 = 0.f, d1 = 0.f, d2 = 0.f, d3 = 0.f;
        #pragma unroll
        for (int i = 0; i < 4; i++) {
            m2 = fmaf(m[i].x, m[i].x, fmaf(m[i].y, m[i].y, fmaf(m[i].z, m[i].z, fmaf(m[i].w, m[i].w, m2))));
            d0 = fmaf(m[i].x, kk[0][i].x, fmaf(m[i].y, kk[0][i].y, fmaf(m[i].z, kk[0][i].z, fmaf(m[i].w, kk[0][i].w, d0))));
            d1 = fmaf(m[i].x, kk[1][i].x, fmaf(m[i].y, kk[1][i].y, fmaf(m[i].z, kk[1][i].z, fmaf(m[i].w, kk[1][i].w, d1))));
            d2 = fmaf(m[i].x, kk[2][i].x, fmaf(m[i].y, kk[2][i].y, fmaf(m[i].z, kk[2][i].z, fmaf(m[i].w, kk[2][i].w, d2))));
            d3 = fmaf(m[i].x, kk[3][i].x, fmaf(m[i].y, kk[3][i].y, fmaf(m[i].z, kk[3][i].z, fmaf(m[i].w, kk[3][i].w, d3))));
        }
        // reduce within each 8-lane group (3 levels)
        #pragma unroll
        for (int o = 4; o; o >>= 1) {
            m2 += __shfl_xor_sync(0xFFFFFFFFu, m2, o);
            d0 += __shfl_xor_sync(0xFFFFFFFFu, d0, o);
            d1 += __shfl_xor_sync(0xFFFFFFFFu, d1, o);
            d2 += __shfl_xor_sync(0xFFFFFFFFu, d2, o);
            d3 += __shfl_xor_sync(0xFFFFFFFFu, d3, o);
        }
        if (sub == 0) {
            float nm = sqrtf(m2);
            g_scores[(b * HH + 0) * NN + n] = d0 / (kn[0] * nm + EPSF);
            g_scores[(b * HH + 1) * NN + n] = d1 / (kn[1] * nm + EPSF);
            g_scores[(b * HH + 2) * NN + n] = d2 / (kn[2] * nm + EPSF);
            g_scores[(b * HH + 3) * NN + n] = d3 / (kn[3] * nm + EPSF);
        }
    }
}

// -------------- Kernel C: softmax/interp/shift/sharpen/renorm --------------
__global__ void kC_weights() {
    __shared__ float sm[NN];
    __shared__ float red[16];
    int bh = blockIdx.x;
    int h = bh & 3;
    int tid = threadIdx.x;

    float beta  = g_beta[bh];
    float gate  = g_gate[bh];
    float gamma = g_gamma[bh];
    float s0 = g_shift[bh * 3 + 0];
    float s1 = g_shift[bh * 3 + 1];
    float s2 = g_shift[bh * 3 + 2];

    float v[8], mx = -INFINITY;
    #pragma unroll
    for (int k = 0; k < 8; k++) {
        v[k] = g_scores[bh * NN + tid + k * 512] * beta;
        mx = fmaxf(mx, v[k]);
    }
    mx = blockReduceMax<16>(mx, red, tid);
    float s = 0.f;
    #pragma unroll
    for (int k = 0; k < 8; k++) { v[k] = __expf(v[k] - mx); s += v[k]; }
    s = blockReduceSum<16>(s, red, tid);
    float invS = 1.f / s;
    float omg = 1.f - gate;
    #pragma unroll
    for (int k = 0; k < 8; k++) {
        int n = tid + k * 512;
        sm[n] = gate * v[k] * invS + omg * g_prev[h * NN + n];
    }
    __syncthreads();
    float t = 0.f, ws[8];
    #pragma unroll
    for (int k = 0; k < 8; k++) {
        int n = tid + k * 512;
        float wsh = s0 * sm[(n - 1) & (NN - 1)] + s1 * sm[n] + s2 * sm[(n + 1) & (NN - 1)];
        float p = exp2f(gamma * __log2f(wsh));  // wsh==0 -> -inf -> 0 (matches ref underflow)
        ws[k] = p;
        t += p;
    }
    t = blockReduceSum<16>(t, red, tid);
    float invT = 1.f / (t + EPSF);
    #pragma unroll
    for (int k = 0; k < 8; k++)
        g_wd[bh * NN + tid + k * 512] = ws[k] * invT;
}

// -------------- Kernel D: memory pass 2 -> erase/update/write --------------
// grid (32, B), block 256. Each warp: 16 rows in 4 groups of 4 (batched loads).
__global__ void kD_apply(const float* __restrict__ memory, float* __restrict__ out) {
    int b = blockIdx.y;
    int tid = threadIdx.x;
    int lane = tid & 31, warp = tid >> 5;

    float4 ea[HH], wa[HH];
    #pragma unroll
    for (int h = 0; h < HH; h++) {
        ea[h] = *(const float4*)&g_erase[(b * HH + h) * WW + lane * 4];
        wa[h] = *(const float4*)&g_write[(b * HH + h) * WW + lane * 4];
    }

    int wi = blockIdx.x * 8 + warp;    // 0..255
    int n0 = wi * 16;
    #pragma unroll
    for (int g = 0; g < 4; g++) {
        int nb = n0 + g * 4;
        float4 m[4];
        float  wd[4][HH];
        #pragma unroll
        for (int r = 0; r < 4; r++) {
            size_t off = ((size_t)(b * NN + nb + r)) * WW + lane * 4;
            m[r] = __ldcs((const float4*)(memory + off));
            #pragma unroll
            for (int h = 0; h < HH; h++)
                wd[r][h] = __ldg(&g_wd[(b * HH + h) * NN + nb + r]);
        }
        #pragma unroll
        for (int r = 0; r < 4; r++) {
            float4 o;
            o.x = m[r].x * ((1.f - wd[r][0]*ea[0].x) * (1.f - wd[r][1]*ea[1].x) * (1.f - wd[r][2]*ea[2].x) * (1.f - wd[r][3]*ea[3].x))
                + (wd[r][0]*wa[0].x + wd[r][1]*wa[1].x + wd[r][2]*wa[2].x + wd[r][3]*wa[3].x);
            o.y = m[r].y * ((1.f - wd[r][0]*ea[0].y) * (1.f - wd[r][1]*ea[1].y) * (1.f - wd[r][2]*ea[2].y) * (1.f - wd[r][3]*ea[3].y))
                + (wd[r][0]*wa[0].y + wd[r][1]*wa[1].y + wd[r][2]*wa[2].y + wd[r][3]*wa[3].y);
            o.z = m[r].z * ((1.f - wd[r][0]*ea[0].z) * (1.f - wd[r][1]*ea[1].z) * (1.f - wd[r][2]*ea[2].z) * (1.f - wd[r][3]*ea[3].z))
                + (wd[r][0]*wa[0].z + wd[r][1]*wa[1].z + wd[r][2]*wa[2].z + wd[r][3]*wa[3].z);
            o.w = m[r].w * ((1.f - wd[r][0]*ea[0].w) * (1.f - wd[r][1]*ea[1].w) * (1.f - wd[r][2]*ea[2].w) * (1.f - wd[r][3]*ea[3].w))
                + (wd[r][0]*wa[0].w + wd[r][1]*wa[1].w + wd[r][2]*wa[2].w + wd[r][3]*wa[3].w);
            size_t off = ((size_t)(b * NN + nb + r)) * WW + lane * 4;
            __stcs((float4*)(out + off), o);
        }
    }
}

// ---------------------------------------------------------------------------
extern "C" void kernel_launch(void* const* d_in, const int* in_sizes, int n_in,
                              void* d_out, int out_size) {
    const float* memory   = (const float*)d_in[0];   // [B,N,W]
    const float* controls = (const float*)d_in[1];   // [B, H*(3W+6)]
    const float* bias     = (const float*)d_in[2];   // [1,H,N]
    float* out = (float*)d_out;                      // [B,N,W]

    kA_controls<<<BB * HH, 128>>>(controls);
    kP_prev<<<HH, 1024>>>(bias);
    kB_scores<<<dim3(32, BB), 256>>>(memory);
    kC_weights<<<BB * HH, 512>>>();
    kD_apply<<<dim3(32, BB), 256>>>(memory, out);
}

// round 10
// speedup vs baseline: 1.2649x; 1.1536x over previous
#include <cuda_runtime.h>
#include <math.h>

#define BB 128
#define HH 4
#define NN 4096
#define WW 128
#define CTRL 1560          // H*(3*W+6)
#define EPSF 1e-8f
#define T 512              // threads per block (16 warps)

__device__ __forceinline__ float softplusf(float x) {
    return (x > 20.f) ? x : log1pf(expf(x));
}
__device__ __forceinline__ float sigmoidf(float x) {
    return 1.f / (1.f + expf(-x));
}

// block-wide reductions over 512 threads (16 warps)
__device__ __forceinline__ float blockReduceSum16(float v, float* red, int tid) {
    int lane = tid & 31, wid = tid >> 5;
    #pragma unroll
    for (int o = 16; o; o >>= 1) v += __shfl_xor_sync(0xFFFFFFFFu, v, o);
    if (lane == 0) red[wid] = v;
    __syncthreads();
    float r = (tid < 16) ? red[tid] : 0.f;
    if (wid == 0) {
        #pragma unroll
        for (int o = 16; o; o >>= 1) r += __shfl_xor_sync(0xFFFFFFFFu, r, o);
        if (lane == 0) red[0] = r;
    }
    __syncthreads();
    float outv = red[0];
    __syncthreads();
    return outv;
}
__device__ __forceinline__ float blockReduceMax16(float v, float* red, int tid) {
    int lane = tid & 31, wid = tid >> 5;
    #pragma unroll
    for (int o = 16; o; o >>= 1) v = fmaxf(v, __shfl_xor_sync(0xFFFFFFFFu, v, o));
    if (lane == 0) red[wid] = v;
    __syncthreads();
    float r = (tid < 16) ? red[tid] : -INFINITY;
    if (wid == 0) {
        #pragma unroll
        for (int o = 16; o; o >>= 1) r = fmaxf(r, __shfl_xor_sync(0xFFFFFFFFu, r, o));
        if (lane == 0) red[0] = r;
    }
    __syncthreads();
    float outv = red[0];
    __syncthreads();
    return outv;
}

// ============ ONE fused kernel: block b handles batch b end-to-end ==========
__global__ __launch_bounds__(T) void fused_writehead(
    const float* __restrict__ memory,     // [B,N,W]
    const float* __restrict__ controls,   // [B,CTRL]
    const float* __restrict__ bias,       // [H,N]
    float* __restrict__ out)              // [B,N,W]
{
    extern __shared__ float s[];          // [HH*NN] scores -> weights (64 KB)
    __shared__ float kbuf[HH * WW];
    __shared__ float ebuf[HH * WW];
    __shared__ float wbuf[HH * WW];
    __shared__ float red[16];
    __shared__ float kn_s[HH], beta_s[HH], gate_s[HH], gamma_s[HH];
    __shared__ float sh_s[HH][3];

    const int b    = blockIdx.x;
    const int tid  = threadIdx.x;
    const int lane = tid & 31;
    const int warp = tid >> 5;

    // ---------------- prologue: control activations (1 value/thread) -------
    {
        const float* c = controls + b * CTRL;
        int h = tid >> 7, w = tid & 127;
        float kv = tanhf(c[h * WW + w]);
        kbuf[tid] = kv;
        ebuf[tid] = sigmoidf(c[512 + h * WW + w]);
        wbuf[tid] = tanhf(c[1024 + h * WW + w]);

        float ss = kv * kv;
        #pragma unroll
        for (int o = 16; o; o >>= 1) ss += __shfl_xor_sync(0xFFFFFFFFu, ss, o);
        if (lane == 0) red[warp] = ss;   // warps 4h..4h+3 hold head h partials
        __syncthreads();
        if (tid < HH) {
            int h4 = tid * 4;
            kn_s[tid]   = sqrtf(red[h4] + red[h4 + 1] + red[h4 + 2] + red[h4 + 3]);
            beta_s[tid]  = softplusf(c[1536 + tid]);
            gate_s[tid]  = sigmoidf(c[1540 + tid]);
            gamma_s[tid] = 1.f + softplusf(c[1556 + tid]);
            float a0 = c[1544 + tid * 3 + 0];
            float a1 = c[1544 + tid * 3 + 1];
            float a2 = c[1544 + tid * 3 + 2];
            float m = fmaxf(a0, fmaxf(a1, a2));
            float e0 = expf(a0 - m), e1 = expf(a1 - m), e2 = expf(a2 - m);
            float inv = 1.f / (e0 + e1 + e2);
            sh_s[tid][0] = e0 * inv; sh_s[tid][1] = e1 * inv; sh_s[tid][2] = e2 * inv;
        }
        __syncthreads();
    }

    const float* memb = memory + (size_t)b * NN * WW;

    // ---------------- pass 1: cosine scores into smem -----------------------
    {
        const int sub  = lane & 7;     // 16-float chunk of the row
        const int rsel = lane >> 3;    // row within 4-row group
        float4 kk[HH][4];
        float  kn[HH];
        #pragma unroll
        for (int h = 0; h < HH; h++) {
            const float* kp = &kbuf[h * WW + sub * 16];
            #pragma unroll
            for (int i = 0; i < 4; i++) kk[h][i] = *(const float4*)(kp + 4 * i);
            kn[h] = kn_s[h];
        }
        for (int it = 0; it < NN / 64; it++) {
            int n = it * 64 + warp * 4 + rsel;
            const float* rp = memb + (size_t)n * WW + sub * 16;
            float4 m[4];
            #pragma unroll
            for (int i = 0; i < 4; i++) m[i] = *(const float4*)(rp + 4 * i);  // keep in L2

            float m2 = 0.f, d0 = 0.f, d1 = 0.f, d2 = 0.f, d3 = 0.f;
            #pragma unroll
            for (int i = 0; i < 4; i++) {
                m2 = fmaf(m[i].x, m[i].x, fmaf(m[i].y, m[i].y, fmaf(m[i].z, m[i].z, fmaf(m[i].w, m[i].w, m2))));
                d0 = fmaf(m[i].x, kk[0][i].x, fmaf(m[i].y, kk[0][i].y, fmaf(m[i].z, kk[0][i].z, fmaf(m[i].w, kk[0][i].w, d0))));
                d1 = fmaf(m[i].x, kk[1][i].x, fmaf(m[i].y, kk[1][i].y, fmaf(m[i].z, kk[1][i].z, fmaf(m[i].w, kk[1][i].w, d1))));
                d2 = fmaf(m[i].x, kk[2][i].x, fmaf(m[i].y, kk[2][i].y, fmaf(m[i].z, kk[2][i].z, fmaf(m[i].w, kk[2][i].w, d2))));
                d3 = fmaf(m[i].x, kk[3][i].x, fmaf(m[i].y, kk[3][i].y, fmaf(m[i].z, kk[3][i].z, fmaf(m[i].w, kk[3][i].w, d3))));
            }
            #pragma unroll
            for (int o = 4; o; o >>= 1) {
                m2 += __shfl_xor_sync(0xFFFFFFFFu, m2, o);
                d0 += __shfl_xor_sync(0xFFFFFFFFu, d0, o);
                d1 += __shfl_xor_sync(0xFFFFFFFFu, d1, o);
                d2 += __shfl_xor_sync(0xFFFFFFFFu, d2, o);
                d3 += __shfl_xor_sync(0xFFFFFFFFu, d3, o);
            }
            if (sub == 0) {
                float nm = sqrtf(m2);
                s[0 * NN + n] = d0 / (kn[0] * nm + EPSF);
                s[1 * NN + n] = d1 / (kn[1] * nm + EPSF);
                s[2 * NN + n] = d2 / (kn[2] * nm + EPSF);
                s[3 * NN + n] = d3 / (kn[3] * nm + EPSF);
            }
        }
        __syncthreads();
    }

    // ------------- weight pipeline per head (all in smem) -------------------
    for (int h = 0; h < HH; h++) {
        float beta  = beta_s[h];
        float gate  = gate_s[h];
        float gamma = gamma_s[h];
        float s0 = sh_s[h][0], s1 = sh_s[h][1], s2 = sh_s[h][2];
        const float* bp = bias + h * NN;
        float* sh = s + h * NN;

        // prev = softmax(bias[h]) computed on the fly
        float bv[8], bmax = -INFINITY;
        #pragma unroll
        for (int k = 0; k < 8; k++) {
            bv[k] = bp[tid + k * T];
            bmax = fmaxf(bmax, bv[k]);
        }
        bmax = blockReduceMax16(bmax, red, tid);
        float bs = 0.f;
        #pragma unroll
        for (int k = 0; k < 8; k++) { bv[k] = __expf(bv[k] - bmax); bs += bv[k]; }
        bs = blockReduceSum16(bs, red, tid);
        float invB = 1.f / bs;

        // softmax(scores*beta)
        float v[8], mx = -INFINITY;
        #pragma unroll
        for (int k = 0; k < 8; k++) {
            v[k] = sh[tid + k * T] * beta;
            mx = fmaxf(mx, v[k]);
        }
        mx = blockReduceMax16(mx, red, tid);
        float sum = 0.f;
        #pragma unroll
        for (int k = 0; k < 8; k++) { v[k] = __expf(v[k] - mx); sum += v[k]; }
        sum = blockReduceSum16(sum, red, tid);
        float invS = 1.f / sum;
        float omg = 1.f - gate;
        #pragma unroll
        for (int k = 0; k < 8; k++) {
            int n = tid + k * T;
            sh[n] = gate * v[k] * invS + omg * bv[k] * invB;   // w_interp
        }
        __syncthreads();

        // circular shift + sharpen + renorm
        float t = 0.f, ws[8];
        #pragma unroll
        for (int k = 0; k < 8; k++) {
            int n = tid + k * T;
            float wsh = s0 * sh[(n - 1) & (NN - 1)] + s1 * sh[n] + s2 * sh[(n + 1) & (NN - 1)];
            float p = exp2f(gamma * __log2f(wsh));   // wsh==0 -> 0, matches fp32 underflow
            ws[k] = p;
            t += p;
        }
        t = blockReduceSum16(t, red, tid);           // internal syncs cover WAR hazard
        float invT = 1.f / (t + EPSF);
        #pragma unroll
        for (int k = 0; k < 8; k++)
            sh[tid + k * T] = ws[k] * invT;          // final write_dist
    }
    __syncthreads();

    // ---------------- pass 2: erase/update/write (reverse order) ------------
    {
        float4 ea[HH], wa[HH];
        #pragma unroll
        for (int h = 0; h < HH; h++) {
            ea[h] = *(const float4*)&ebuf[h * WW + lane * 4];
            wa[h] = *(const float4*)&wbuf[h * WW + lane * 4];
        }
        float* outb = out + (size_t)b * NN * WW;
        // warp covers rows [warp*256, warp*256+256), high groups first (L2 recency)
        for (int j = 63; j >= 0; j--) {
            int nb = warp * 256 + j * 4;
            float4 m[4];
            float  wd[4][HH];
            #pragma unroll
            for (int r = 0; r < 4; r++) {
                size_t off = (size_t)(nb + r) * WW + lane * 4;
                m[r] = __ldcs((const float4*)(memb + off));
                #pragma unroll
                for (int h = 0; h < HH; h++)
                    wd[r][h] = s[h * NN + nb + r];    // smem broadcast
            }
            #pragma unroll
            for (int r = 0; r < 4; r++) {
                float4 o;
                o.x = m[r].x * ((1.f - wd[r][0]*ea[0].x) * (1.f - wd[r][1]*ea[1].x) * (1.f - wd[r][2]*ea[2].x) * (1.f - wd[r][3]*ea[3].x))
                    + (wd[r][0]*wa[0].x + wd[r][1]*wa[1].x + wd[r][2]*wa[2].x + wd[r][3]*wa[3].x);
                o.y = m[r].y * ((1.f - wd[r][0]*ea[0].y) * (1.f - wd[r][1]*ea[1].y) * (1.f - wd[r][2]*ea[2].y) * (1.f - wd[r][3]*ea[3].y))
                    + (wd[r][0]*wa[0].y + wd[r][1]*wa[1].y + wd[r][2]*wa[2].y + wd[r][3]*wa[3].y);
                o.z = m[r].z * ((1.f - wd[r][0]*ea[0].z) * (1.f - wd[r][1]*ea[1].z) * (1.f - wd[r][2]*ea[2].z) * (1.f - wd[r][3]*ea[3].z))
                    + (wd[r][0]*wa[0].z + wd[r][1]*wa[1].z + wd[r][2]*wa[2].z + wd[r][3]*wa[3].z);
                o.w = m[r].w * ((1.f - wd[r][0]*ea[0].w) * (1.f - wd[r][1]*ea[1].w) * (1.f - wd[r][2]*ea[2].w) * (1.f - wd[r][3]*ea[3].w))
                    + (wd[r][0]*wa[0].w + wd[r][1]*wa[1].w + wd[r][2]*wa[2].w + wd[r][3]*wa[3].w);
                size_t off = (size_t)(nb + r) * WW + lane * 4;
                __stcs((float4*)(outb + off), o);
            }
        }
    }
}

// ---------------------------------------------------------------------------
extern "C" void kernel_launch(void* const* d_in, const int* in_sizes, int n_in,
                              void* d_out, int out_size) {
    const float* memory   = (const float*)d_in[0];   // [B,N,W]
    const float* controls = (const float*)d_in[1];   // [B,CTRL]
    const float* bias     = (const float*)d_in[2];   // [1,H,N]
    float* out = (float*)d_out;                      // [B,N,W]

    const int smem = HH * NN * sizeof(float);        // 64 KB dynamic
    cudaFuncSetAttribute(fused_writehead,
                         cudaFuncAttributeMaxDynamicSharedMemorySize, smem);
    fused_writehead<<<BB, T, smem>>>(memory, controls, bias, out);
}